// round 16
// baseline (speedup 1.0000x reference)
#include <cuda_runtime.h>
#include <cuda_bf16.h>
#include <cstdint>
#include <math.h>

#define N 8192
#define D 512
#define TEMP_INV 10.0f

#define NB    64          // 128-row bands
#define NTT   2080        // NB*(NB+1)/2 upper-triangle tiles
#define G2    296         // CTAs (2 per SM)
#define TPB   256
#define RT    8           // per-slot top-K kept
#define SEL   12          // candidates rescored exactly
#define CSTR  68          // C staging row stride in words (64 + 4 pad)

// ---- device scratch (static; no allocations allowed) ----
__device__ float    g_Xn[N * D];        // 16 MB fp32 normalized (exact rescore)
// g_X8: block-swizzled e4m3. Block (band, chunk) = contiguous 16 KB holding
// rows [band*128, +128) x K [chunk*128, +128) in the smem image layout.
__device__ uint8_t  g_X8[N * D];
__device__ float2   g_cand[N * 64 * 8]; // candidate table (val, idx)
__device__ int      g_ticket;           // work-stealing counter

// ---- SMEM: A dbl 2x16K | B dbl 2x16K | C bf16 (128 x 68 words) | barriers ----
#define SM_A0  0
#define SM_A1  16384
#define SM_B0  32768
#define SM_B1  49152
#define SM_C   65536
#define SM_MB  (SM_C + 128 * CSTR * 4)        // 100352: mbF0,mbF1,mbE0,mbE1
#define SMEM_TOTAL (SM_MB + 64)               // 100416 B (x2 CTAs < 227 KB)

// ================= helpers =================
__device__ __forceinline__ uint32_t smem_u32(const void* p) {
    uint32_t a;
    asm("{ .reg .u64 t; cvta.to.shared.u64 t, %1; cvt.u32.u64 %0, t; }" : "=r"(a) : "l"(p));
    return a;
}
__device__ __forceinline__ void ldsm4(uint32_t* r, uint32_t addr) {
    asm volatile("ldmatrix.sync.aligned.m8n8.x4.shared.b16 {%0,%1,%2,%3}, [%4];"
                 : "=r"(r[0]), "=r"(r[1]), "=r"(r[2]), "=r"(r[3]) : "r"(addr));
}
__device__ __forceinline__ void mma_fp8(float* c, const uint32_t* a, const uint32_t* b) {
    asm volatile("mma.sync.aligned.m16n8k32.row.col.f32.e4m3.e4m3.f32 "
                 "{%0,%1,%2,%3}, {%4,%5,%6,%7}, {%8,%9}, {%0,%1,%2,%3};"
                 : "+f"(c[0]), "+f"(c[1]), "+f"(c[2]), "+f"(c[3])
                 : "r"(a[0]), "r"(a[1]), "r"(a[2]), "r"(a[3]), "r"(b[0]), "r"(b[1]));
}
__device__ __forceinline__ uint32_t pack4_e4m3(float x, float y, float z, float w) {
    uint16_t lo, hi;
    asm("cvt.rn.satfinite.e4m3x2.f32 %0, %1, %2;" : "=h"(lo) : "f"(y), "f"(x));
    asm("cvt.rn.satfinite.e4m3x2.f32 %0, %1, %2;" : "=h"(hi) : "f"(w), "f"(z));
    return (uint32_t)lo | ((uint32_t)hi << 16);
}
__device__ __forceinline__ uint32_t pack_bf16x2(float even, float odd) {
    uint32_t r;   // hi = odd, lo = even
    asm("cvt.rn.bf16x2.f32 %0, %1, %2;" : "=r"(r) : "f"(odd), "f"(even));
    return r;
}
__device__ __forceinline__ float bflo(uint32_t w) { return __uint_as_float(w << 16); }
__device__ __forceinline__ float bfhi(uint32_t w) { return __uint_as_float(w & 0xFFFF0000u); }
__device__ __forceinline__ __nv_bfloat162 as_bf2(uint32_t w) {
    return *reinterpret_cast<const __nv_bfloat162*>(&w);
}

#define MBAR_INIT(a, c) \
    asm volatile("mbarrier.init.shared.b64 [%0], %1;" :: "r"(a), "r"(c) : "memory")
#define MBAR_EXPECT(a, bytes) \
    asm volatile("mbarrier.arrive.expect_tx.shared.b64 _, [%0], %1;" :: "r"(a), "r"(bytes) : "memory")
#define MBAR_ARRIVE(a) \
    asm volatile("mbarrier.arrive.shared.b64 _, [%0];" :: "r"(a) : "memory")
#define MBAR_WAIT(addr, par) do {                                                   \
    uint32_t _m = (addr), _p = (par), _d;                                           \
    asm volatile("{ .reg .pred p; mbarrier.try_wait.parity.acquire.cta.shared::cta.b64 p, [%1], %2; selp.b32 %0,1,0,p; }" \
        : "=r"(_d) : "r"(_m), "r"(_p) : "memory");                                  \
    if (!_d) {                                                                      \
        asm volatile("{ .reg .pred P1; WL_%=: mbarrier.try_wait.parity.acquire.cta.shared::cta.b64 P1, [%0], %1, 0x989680; @P1 bra.uni WD_%=; bra.uni WL_%=; WD_%=: }" \
            :: "r"(_m), "r"(_p) : "memory");                                        \
    } } while (0)
#define BULK16K(dst, src, mb) \
    asm volatile("cp.async.bulk.shared::cta.global.mbarrier::complete_tx::bytes [%0], [%1], 16384, [%2];" \
        :: "r"(dst), "l"(src), "r"(mb) : "memory")

__device__ __forceinline__ void decode_tile(int t, int& i, int& j) {
    int rem = t, ii = 0;
    while (rem >= NB - ii) { rem -= NB - ii; ii++; }
    i = ii; j = ii + rem;
}

// ===========================================================================
// Kernel 1: L2-normalize rows -> fp32 + block-swizzled e4m3(x16); reset ticket.
// ===========================================================================
__global__ void normalize_kernel(const float* __restrict__ X) {
    if (blockIdx.x == 0 && threadIdx.x == 0) g_ticket = 0;

    int row  = blockIdx.x * 8 + (threadIdx.x >> 5);
    int lane = threadIdx.x & 31;
    const float4* src = reinterpret_cast<const float4*>(X + (size_t)row * D);

    float4 v[4];
    float s = 0.0f;
#pragma unroll
    for (int i = 0; i < 4; i++) {
        v[i] = src[i * 32 + lane];
        s += v[i].x*v[i].x + v[i].y*v[i].y + v[i].z*v[i].z + v[i].w*v[i].w;
    }
#pragma unroll
    for (int o = 16; o; o >>= 1) s += __shfl_xor_sync(0xffffffffu, s, o);
    float scale = 1.0f / fmaxf(sqrtf(s), 1e-12f);

    float4* dst = reinterpret_cast<float4*>(g_Xn + (size_t)row * D);
    const int band = row >> 7, r = row & 127;
    const int seg = lane >> 2, word = lane & 3;
    const uint32_t swoff = (uint32_t)(r * 128 + ((seg ^ (r & 7)) << 4) + word * 4);
#pragma unroll
    for (int i = 0; i < 4; i++) {     // i = K-chunk
        v[i].x *= scale; v[i].y *= scale; v[i].z *= scale; v[i].w *= scale;
        dst[i * 32 + lane] = v[i];
        *reinterpret_cast<uint32_t*>(
            g_X8 + (size_t)(band * 4 + i) * 16384 + swoff) =
            pack4_e4m3(16.f * v[i].x, 16.f * v[i].y, 16.f * v[i].z, 16.f * v[i].w);
    }
}

// ===========================================================================
// Kernel 2: symmetric-triangle fp8 GEMM; barrier-free pipelined mainloop
// (full/empty mbarriers, warp-slip), bulk-copy loads, work-stealing tiles,
// SIMD-max scans.  8 warps, 2 CTAs/SM.  Only 2 __syncthreads per tile.
// ===========================================================================
__global__ __launch_bounds__(TPB, 2) void tile_kernel(float* __restrict__ out) {
    extern __shared__ char smem[];
    __shared__ int s_next;
    const uint32_t sb = smem_u32(smem);
    uint32_t* CsW = reinterpret_cast<uint32_t*>(smem + SM_C);   // [128][CSTR] bf16x2

    const int tid = threadIdx.x, wid = tid >> 5, lane = tid & 31;
    const int wr = wid >> 1, wc = wid & 1;

    // ldmatrix lane mapping (16B seg = 16 fp8 = k16)
    const int grp = lane >> 3, l7 = lane & 7;
    const int a_r = ((grp & 1) << 3) | l7, a_s = grp >> 1;
    const int b_n = ((grp >> 1) << 3) | l7, b_s = grp & 1;

    const uint32_t mbF0 = sb + SM_MB,      mbF1 = sb + SM_MB + 8;
    const uint32_t mbE0 = sb + SM_MB + 16, mbE1 = sb + SM_MB + 24;
    int pf0 = 0, pf1 = 0;      // full-barrier phases (per thread)
    int pe0 = 0, pe1 = 0;      // empty-barrier phases (tid0 only uses)

    if (tid == 0) {
        MBAR_INIT(mbF0, 1); MBAR_INIT(mbF1, 1);
        MBAR_INIT(mbE0, 8); MBAR_INIT(mbE1, 8);   // one arrival per warp
        s_next = atomicAdd(&g_ticket, 1);
    }
    __syncthreads();
    int t = s_next;
    int i = 0, j = 0;
    if (t < NTT) {
        decode_tile(t, i, j);
        if (tid == 0) {   // prologue: chunks 0 and 1 in flight
            MBAR_EXPECT(mbF0, 32768);
            BULK16K(sb + SM_A0, g_X8 + (size_t)(i * 4 + 0) * 16384, mbF0);
            BULK16K(sb + SM_B0, g_X8 + (size_t)(j * 4 + 0) * 16384, mbF0);
            MBAR_EXPECT(mbF1, 32768);
            BULK16K(sb + SM_A1, g_X8 + (size_t)(i * 4 + 1) * 16384, mbF1);
            BULK16K(sb + SM_B1, g_X8 + (size_t)(j * 4 + 1) * 16384, mbF1);
        }
    }
    __syncthreads();   // t visible to all

    while (t < NTT) {
        float acc[2][8][4];
#pragma unroll
        for (int mf = 0; mf < 2; mf++)
#pragma unroll
            for (int nf = 0; nf < 8; nf++)
#pragma unroll
                for (int ri = 0; ri < 4; ri++) acc[mf][nf][ri] = 0.0f;

        int nt = t, ni = i, nj = j;   // tid0-authoritative; others refresh later
        for (int kc = 0; kc < 4; kc++) {
            const int b = kc & 1;
            if (b == 0) { MBAR_WAIT(mbF0, (uint32_t)pf0); pf0 ^= 1; }
            else        { MBAR_WAIT(mbF1, (uint32_t)pf1); pf1 ^= 1; }

            if (kc == 0 && tid == 0) {
                int x = atomicAdd(&g_ticket, 1);
                s_next = x; nt = x;
                if (x < NTT) decode_tile(x, ni, nj);
            }

            const uint32_t abase = sb + (b ? SM_A1 : SM_A0);
            const uint32_t bbase = sb + (b ? SM_B1 : SM_B0);

#pragma unroll
            for (int ks = 0; ks < 4; ks++) {
                const int sg = ks * 2;
                uint32_t a0[4], a1[4];
                {
                    int r0 = wr * 32 + a_r;
                    ldsm4(a0, abase + r0 * 128 + (((sg + a_s) ^ (r0 & 7)) << 4));
                    int r1 = r0 + 16;
                    ldsm4(a1, abase + r1 * 128 + (((sg + a_s) ^ (r1 & 7)) << 4));
                }
                uint32_t bfr[4][4];
#pragma unroll
                for (int q = 0; q < 4; q++) {
                    int n = wc * 64 + q * 16 + b_n;
                    ldsm4(bfr[q], bbase + n * 128 + (((sg + b_s) ^ (n & 7)) << 4));
                }
#pragma unroll
                for (int nf = 0; nf < 8; nf++) {
                    mma_fp8(acc[0][nf], a0, &bfr[nf >> 1][(nf & 1) * 2]);
                    mma_fp8(acc[1][nf], a1, &bfr[nf >> 1][(nf & 1) * 2]);
                }
            }

            // warp done reading buffer b for this chunk
            if (lane == 0) MBAR_ARRIVE(b ? mbE1 : mbE0);

            // producer: refill buffer b with stream-chunk kc+2
            if (tid == 0) {
                int ck, bi_, bj_; bool go;
                if (kc < 2) { go = true;       ck = kc + 2; bi_ = i;  bj_ = j;  }
                else        { go = (nt < NTT); ck = kc - 2; bi_ = ni; bj_ = nj; }
                if (go) {
                    if (b == 0) { MBAR_WAIT(mbE0, (uint32_t)pe0); pe0 ^= 1; }
                    else        { MBAR_WAIT(mbE1, (uint32_t)pe1); pe1 ^= 1; }
                    uint32_t mf_ = b ? mbF1 : mbF0;
                    MBAR_EXPECT(mf_, 32768);
                    BULK16K(abase, g_X8 + (size_t)(bi_ * 4 + ck) * 16384, mf_);
                    BULK16K(bbase, g_X8 + (size_t)(bj_ * 4 + ck) * 16384, mf_);
                }
            }
        }

        __syncthreads();   // (1) prev scans done -> CsW writable; s_next visible
        nt = s_next;
        if (nt < NTT) decode_tile(nt, ni, nj);

        // ---- stage C: word w' = wc*32 + (lane&3)*8 + nf  (nf-contiguous) ----
#pragma unroll
        for (int mf = 0; mf < 2; mf++)
#pragma unroll
            for (int rp = 0; rp < 2; rp++) {
                int r = wr * 32 + mf * 16 + (lane >> 2) + rp * 8;
                uint32_t* dst = CsW + r * CSTR + wc * 32 + (lane & 3) * 8;
                uint4 w0, w1;
                w0.x = pack_bf16x2(acc[mf][0][rp*2], acc[mf][0][rp*2+1]);
                w0.y = pack_bf16x2(acc[mf][1][rp*2], acc[mf][1][rp*2+1]);
                w0.z = pack_bf16x2(acc[mf][2][rp*2], acc[mf][2][rp*2+1]);
                w0.w = pack_bf16x2(acc[mf][3][rp*2], acc[mf][3][rp*2+1]);
                w1.x = pack_bf16x2(acc[mf][4][rp*2], acc[mf][4][rp*2+1]);
                w1.y = pack_bf16x2(acc[mf][5][rp*2], acc[mf][5][rp*2+1]);
                w1.z = pack_bf16x2(acc[mf][6][rp*2], acc[mf][6][rp*2+1]);
                w1.w = pack_bf16x2(acc[mf][7][rp*2], acc[mf][7][rp*2+1]);
                *reinterpret_cast<uint4*>(dst)     = w0;
                *reinterpret_cast<uint4*>(dst + 4) = w1;
            }
        __syncthreads();   // (2) staging -> scan

        // ---- zero-fill output blocks (i,j) and mirror (fire & forget) ----
        {
            const float4 z = make_float4(0.f, 0.f, 0.f, 0.f);
#pragma unroll
            for (int q = 0; q < 16; q++) {
                int lin = tid + q * TPB;
                int r = lin >> 5, c4 = lin & 31;
                *reinterpret_cast<float4*>(out + (size_t)(i * 128 + r) * N + j * 128 + c4 * 4) = z;
            }
            if (i != j) {
#pragma unroll
                for (int q = 0; q < 16; q++) {
                    int lin = tid + q * TPB;
                    int r = lin >> 5, c4 = lin & 31;
                    *reinterpret_cast<float4*>(out + (size_t)(j * 128 + r) * N + i * 128 + c4 * 4) = z;
                }
            }
        }

        // ---- scans with SIMD-max fast path ----
        float tv[RT]; int ti[RT];
#pragma unroll
        for (int q = 0; q < RT; q++) { tv[q] = -1e30f; ti[q] = 0; }

        if (tid < 128) {
            // row scan: row r, 16 groups of 4 words (8 values)
            const int r = tid;
            const uint32_t* base = CsW + r * CSTR;
            for (int g = 0; g < 16; g++) {
                uint4 qw = *reinterpret_cast<const uint4*>(base + 4 * g);
                __nv_bfloat162 m = __hmax2(__hmax2(as_bf2(qw.x), as_bf2(qw.y)),
                                           __hmax2(as_bf2(qw.z), as_bf2(qw.w)));
                float mx = fmaxf(__low2float(m), __high2float(m));
                if (mx > tv[RT - 1]) {
                    uint32_t ws[4] = {qw.x, qw.y, qw.z, qw.w};
#pragma unroll
                    for (int k = 0; k < 4; k++) {
                        int w = 4 * g + k;
                        int c = ((w >> 5) << 6) + ((w & 7) << 3) + (((w >> 3) & 3) << 1);
                        float v0 = bflo(ws[k]), v1 = bfhi(ws[k]);
#pragma unroll
                        for (int h = 0; h < 2; h++) {
                            float v = h ? v1 : v0;
                            if (v > tv[RT - 1]) {
                                tv[RT - 1] = v; ti[RT - 1] = j * 128 + c + h;
#pragma unroll
                                for (int p = RT - 1; p > 0; p--)
                                    if (tv[p] > tv[p - 1]) {
                                        float fv = tv[p]; tv[p] = tv[p-1]; tv[p-1] = fv;
                                        int   fi = ti[p]; ti[p] = ti[p-1]; ti[p-1] = fi;
                                    }
                            }
                        }
                    }
                }
            }
            float2* dst = &g_cand[((size_t)(i * 128 + r) * 64 + j) * 8];
#pragma unroll
            for (int q = 0; q < RT; q++)
                dst[q] = make_float2(tv[q], __int_as_float(ti[q]));
        } else if (i != j) {
            // col scan: col c, 32 groups of 4 rows
            const int c = tid - 128;
            const int cc = c & 63;
            const int wprime = ((c >> 6) << 5) + (((cc >> 1) & 3) << 3) + (cc >> 3);
            const bool odd = cc & 1;
            const uint32_t* base = CsW + wprime;
            for (int g = 0; g < 32; g++) {
                uint32_t w0 = base[(4*g + 0) * CSTR];
                uint32_t w1 = base[(4*g + 1) * CSTR];
                uint32_t w2 = base[(4*g + 2) * CSTR];
                uint32_t w3 = base[(4*g + 3) * CSTR];
                float v0 = odd ? bfhi(w0) : bflo(w0);
                float v1 = odd ? bfhi(w1) : bflo(w1);
                float v2 = odd ? bfhi(w2) : bflo(w2);
                float v3 = odd ? bfhi(w3) : bflo(w3);
                float mx = fmaxf(fmaxf(v0, v1), fmaxf(v2, v3));
                if (mx > tv[RT - 1]) {
                    float vs[4] = {v0, v1, v2, v3};
#pragma unroll
                    for (int k = 0; k < 4; k++) {
                        float v = vs[k];
                        if (v > tv[RT - 1]) {
                            tv[RT - 1] = v; ti[RT - 1] = i * 128 + 4*g + k;
#pragma unroll
                            for (int p = RT - 1; p > 0; p--)
                                if (tv[p] > tv[p - 1]) {
                                    float fv = tv[p]; tv[p] = tv[p-1]; tv[p-1] = fv;
                                    int   fi = ti[p]; ti[p] = ti[p-1]; ti[p-1] = fi;
                                }
                        }
                    }
                }
            }
            float2* dst = &g_cand[((size_t)(j * 128 + c) * 64 + i) * 8];
#pragma unroll
            for (int q = 0; q < RT; q++)
                dst[q] = make_float2(tv[q], __int_as_float(ti[q]));
        }

        t = nt; i = ni; j = nj;
        // CsW reuse protected by next tile's pre-staging __syncthreads
    }
}

// ===========================================================================
// Kernel 3: per-row merge of 64 sorted 8-lists -> top-12, exact fp32 rescore,
// top-5 (jax tie rule), softmax, scatter.  One warp per row.
// ===========================================================================
__global__ __launch_bounds__(256) void merge_rescore(float* __restrict__ out) {
    const int wid = threadIdx.x >> 5, lane = threadIdx.x & 31;
    const int row = blockIdx.x * 8 + wid;

    const float2* base = g_cand + (size_t)row * 512;
    int h0 = 0, h1 = 0;
    float2 e;
    e = base[lane * 8];        float cv0 = e.x; int ci0 = __float_as_int(e.y);
    e = base[(lane + 32) * 8]; float cv1 = e.x; int ci1 = __float_as_int(e.y);

    int selidx[SEL];
#pragma unroll
    for (int it = 0; it < SEL; it++) {
        bool p0 = (cv0 > cv1) || (cv0 == cv1 && ci0 <= ci1);
        float v = p0 ? cv0 : cv1;
        int  ix = p0 ? ci0 : ci1;
        float bv = v; int bi = ix, bl = lane;
#pragma unroll
        for (int o = 16; o; o >>= 1) {
            float ov = __shfl_xor_sync(0xffffffffu, bv, o);
            int   oi = __shfl_xor_sync(0xffffffffu, bi, o);
            int   ol = __shfl_xor_sync(0xffffffffu, bl, o);
            if (ov > bv || (ov == bv && oi < bi)) { bv = ov; bi = oi; bl = ol; }
        }
        selidx[it] = bi;
        if (bl == lane) {
            if (p0) {
                h0++;
                if (h0 < 8) { e = base[lane * 8 + h0]; cv0 = e.x; ci0 = __float_as_int(e.y); }
                else cv0 = -1e30f;
            } else {
                h1++;
                if (h1 < 8) { e = base[(lane + 32) * 8 + h1]; cv1 = e.x; ci1 = __float_as_int(e.y); }
                else cv1 = -1e30f;
            }
        }
    }

    // ---- exact fp32 rescore of the 12 selected ----
    float xr[16];
#pragma unroll
    for (int q = 0; q < 16; q++) xr[q] = g_Xn[(size_t)row * D + q * 32 + lane];

    float myv = -1e30f; int myi = 0x7fffffff;
#pragma unroll
    for (int c = 0; c < SEL; c++) {
        int idx = selidx[c];
        const float* Xc = g_Xn + (size_t)idx * D;
        float s = 0.f;
#pragma unroll
        for (int q = 0; q < 16; q++) s = fmaf(xr[q], Xc[q * 32 + lane], s);
#pragma unroll
        for (int o = 16; o; o >>= 1) s += __shfl_xor_sync(0xffffffffu, s, o);
        if (lane == c) { myv = s; myi = idx; }
    }

    float sv[5]; int si[5];
#pragma unroll
    for (int r5 = 0; r5 < 5; r5++) {
        float v = myv; int ix = myi;
#pragma unroll
        for (int o = 16; o; o >>= 1) {
            float ov = __shfl_xor_sync(0xffffffffu, v, o);
            int   oi = __shfl_xor_sync(0xffffffffu, ix, o);
            if (ov > v || (ov == v && oi < ix)) { v = ov; ix = oi; }
        }
        sv[r5] = v; si[r5] = ix;
        if (myi == ix) { myv = -1e30f; myi = 0x7fffffff; }
    }

    if (lane == 0) {
        float m = sv[0];
        float e0 = expf((sv[0] - m) * TEMP_INV);
        float e1 = expf((sv[1] - m) * TEMP_INV);
        float e2 = expf((sv[2] - m) * TEMP_INV);
        float e3 = expf((sv[3] - m) * TEMP_INV);
        float e4 = expf((sv[4] - m) * TEMP_INV);
        float inv = 1.0f / (e0 + e1 + e2 + e3 + e4);
        float* o = out + (size_t)row * N;
        o[si[0]] = e0 * inv; o[si[1]] = e1 * inv; o[si[2]] = e2 * inv;
        o[si[3]] = e3 * inv; o[si[4]] = e4 * inv;
    }
}

// ===========================================================================
extern "C" void kernel_launch(void* const* d_in, const int* in_sizes, int n_in,
                              void* d_out, int out_size) {
    (void)in_sizes; (void)n_in; (void)out_size;
    const float* X   = (const float*)d_in[0];
    float*       out = (float*)d_out;

    cudaFuncSetAttribute(tile_kernel, cudaFuncAttributeMaxDynamicSharedMemorySize, SMEM_TOTAL);

    normalize_kernel<<<N / 8, 256>>>(X);
    tile_kernel<<<G2, TPB, SMEM_TOTAL>>>(out);
    merge_rescore<<<N / 8, 256>>>(out);
}

// round 17
// speedup vs baseline: 1.1288x; 1.1288x over previous
#include <cuda_runtime.h>
#include <cuda_bf16.h>
#include <cstdint>
#include <math.h>

#define N 8192
#define D 512
#define TEMP_INV 10.0f

#define NB    64          // 128-row bands
#define NTT   2080        // NB*(NB+1)/2 upper-triangle tiles
#define G2    296         // CTAs (2 per SM)
#define TPB   256
#define RT    8           // per-slot top-K kept
#define SEL   12          // candidates rescored exactly
#define CSTR  68          // C staging row stride in words (64 + 4 pad)
#define STAGGER_CYC 40000 // ~half a per-CTA tile period

// ---- device scratch (static; no allocations allowed) ----
__device__ float    g_Xn[N * D];        // 16 MB fp32 normalized (exact rescore)
// g_X8: block-swizzled e4m3. Block (band, chunk) = contiguous 16 KB holding
// rows [band*128, +128) x K [chunk*128, +128) in the smem image layout.
__device__ uint8_t  g_X8[N * D];
__device__ float2   g_cand[N * 64 * 8]; // candidate table (val, idx)
__device__ int      g_ticket;           // work-stealing counter

// ---- SMEM: A dbl 2x16K | B dbl 2x16K | C bf16 (128 x 68 words) | 2 mbar ----
#define SM_A0  0
#define SM_A1  16384
#define SM_B0  32768
#define SM_B1  49152
#define SM_C   65536
#define SM_MB  (SM_C + 128 * CSTR * 4)        // 100352
#define SMEM_TOTAL (SM_MB + 64)               // 100416 B (x2 CTAs < 227 KB)

// ================= helpers =================
__device__ __forceinline__ uint32_t smem_u32(const void* p) {
    uint32_t a;
    asm("{ .reg .u64 t; cvta.to.shared.u64 t, %1; cvt.u32.u64 %0, t; }" : "=r"(a) : "l"(p));
    return a;
}
__device__ __forceinline__ void ldsm4(uint32_t* r, uint32_t addr) {
    asm volatile("ldmatrix.sync.aligned.m8n8.x4.shared.b16 {%0,%1,%2,%3}, [%4];"
                 : "=r"(r[0]), "=r"(r[1]), "=r"(r[2]), "=r"(r[3]) : "r"(addr));
}
__device__ __forceinline__ void mma_fp8(float* c, const uint32_t* a, const uint32_t* b) {
    asm volatile("mma.sync.aligned.m16n8k32.row.col.f32.e4m3.e4m3.f32 "
                 "{%0,%1,%2,%3}, {%4,%5,%6,%7}, {%8,%9}, {%0,%1,%2,%3};"
                 : "+f"(c[0]), "+f"(c[1]), "+f"(c[2]), "+f"(c[3])
                 : "r"(a[0]), "r"(a[1]), "r"(a[2]), "r"(a[3]), "r"(b[0]), "r"(b[1]));
}
__device__ __forceinline__ uint32_t pack4_e4m3(float x, float y, float z, float w) {
    uint16_t lo, hi;
    asm("cvt.rn.satfinite.e4m3x2.f32 %0, %1, %2;" : "=h"(lo) : "f"(y), "f"(x));
    asm("cvt.rn.satfinite.e4m3x2.f32 %0, %1, %2;" : "=h"(hi) : "f"(w), "f"(z));
    return (uint32_t)lo | ((uint32_t)hi << 16);
}
__device__ __forceinline__ uint32_t pack_bf16x2(float even, float odd) {
    uint32_t r;   // hi = odd, lo = even
    asm("cvt.rn.bf16x2.f32 %0, %1, %2;" : "=r"(r) : "f"(odd), "f"(even));
    return r;
}
__device__ __forceinline__ float bflo(uint32_t w) { return __uint_as_float(w << 16); }
__device__ __forceinline__ float bfhi(uint32_t w) { return __uint_as_float(w & 0xFFFF0000u); }
__device__ __forceinline__ __nv_bfloat162 as_bf2(uint32_t w) {
    return *reinterpret_cast<const __nv_bfloat162*>(&w);
}

#define MBAR_INIT(a, c) \
    asm volatile("mbarrier.init.shared.b64 [%0], %1;" :: "r"(a), "r"(c) : "memory")
#define MBAR_EXPECT(a, bytes) \
    asm volatile("mbarrier.arrive.expect_tx.shared.b64 _, [%0], %1;" :: "r"(a), "r"(bytes) : "memory")
#define MBAR_WAIT(addr, par) do {                                                   \
    uint32_t _m = (addr), _p = (par), _d;                                           \
    asm volatile("{ .reg .pred p; mbarrier.try_wait.parity.acquire.cta.shared::cta.b64 p, [%1], %2; selp.b32 %0,1,0,p; }" \
        : "=r"(_d) : "r"(_m), "r"(_p) : "memory");                                  \
    if (!_d) {                                                                      \
        asm volatile("{ .reg .pred P1; WL_%=: mbarrier.try_wait.parity.acquire.cta.shared::cta.b64 P1, [%0], %1, 0x989680; @P1 bra.uni WD_%=; bra.uni WL_%=; WD_%=: }" \
            :: "r"(_m), "r"(_p) : "memory");                                        \
    } } while (0)
#define BULK16K(dst, src, mb) \
    asm volatile("cp.async.bulk.shared::cta.global.mbarrier::complete_tx::bytes [%0], [%1], 16384, [%2];" \
        :: "r"(dst), "l"(src), "r"(mb) : "memory")

__device__ __forceinline__ void decode_tile(int t, int& i, int& j) {
    int rem = t, ii = 0;
    while (rem >= NB - ii) { rem -= NB - ii; ii++; }
    i = ii; j = ii + rem;
}

// ===========================================================================
// Kernel 1: L2-normalize rows -> fp32 + block-swizzled e4m3(x16); reset ticket.
// ===========================================================================
__global__ void normalize_kernel(const float* __restrict__ X) {
    if (blockIdx.x == 0 && threadIdx.x == 0) g_ticket = 0;

    int row  = blockIdx.x * 8 + (threadIdx.x >> 5);
    int lane = threadIdx.x & 31;
    const float4* src = reinterpret_cast<const float4*>(X + (size_t)row * D);

    float4 v[4];
    float s = 0.0f;
#pragma unroll
    for (int i = 0; i < 4; i++) {
        v[i] = src[i * 32 + lane];
        s += v[i].x*v[i].x + v[i].y*v[i].y + v[i].z*v[i].z + v[i].w*v[i].w;
    }
#pragma unroll
    for (int o = 16; o; o >>= 1) s += __shfl_xor_sync(0xffffffffu, s, o);
    float scale = 1.0f / fmaxf(sqrtf(s), 1e-12f);

    float4* dst = reinterpret_cast<float4*>(g_Xn + (size_t)row * D);
    const int band = row >> 7, r = row & 127;
    const int seg = lane >> 2, word = lane & 3;
    const uint32_t swoff = (uint32_t)(r * 128 + ((seg ^ (r & 7)) << 4) + word * 4);
#pragma unroll
    for (int i = 0; i < 4; i++) {     // i = K-chunk
        v[i].x *= scale; v[i].y *= scale; v[i].z *= scale; v[i].w *= scale;
        dst[i * 32 + lane] = v[i];
        *reinterpret_cast<uint32_t*>(
            g_X8 + (size_t)(band * 4 + i) * 16384 + swoff) =
            pack4_e4m3(16.f * v[i].x, 16.f * v[i].y, 16.f * v[i].z, 16.f * v[i].w);
    }
}

// ===========================================================================
// Kernel 2: symmetric-triangle fp8 GEMM; bulk-copy loads, work-stealing tiles,
// SIMD-max scans.  8 warps, 2 CTAs/SM.  Second-wave CTAs staggered ~half a
// tile so co-resident CTAs stay anti-phased (epilogue hides under mainloop).
// ===========================================================================
__global__ __launch_bounds__(TPB, 2) void tile_kernel(float* __restrict__ out) {
    extern __shared__ char smem[];
    __shared__ int s_next;
    const uint32_t sb = smem_u32(smem);
    uint32_t* CsW = reinterpret_cast<uint32_t*>(smem + SM_C);   // [128][CSTR] bf16x2

    const int tid = threadIdx.x, wid = tid >> 5, lane = tid & 31;
    const int wr = wid >> 1, wc = wid & 1;

    // ---- anti-phase stagger: bid and bid+148 co-reside on one SM ----
    if (blockIdx.x >= 148) {
        long long s0 = clock64();
        while (clock64() - s0 < STAGGER_CYC) {}
    }

    // ldmatrix lane mapping (16B seg = 16 fp8 = k16)
    const int grp = lane >> 3, l7 = lane & 7;
    const int a_r = ((grp & 1) << 3) | l7, a_s = grp >> 1;
    const int b_n = ((grp >> 1) << 3) | l7, b_s = grp & 1;

    const uint32_t mb0 = sb + SM_MB, mb1 = sb + SM_MB + 8;
    int ph0 = 0, ph1 = 0;

    if (tid == 0) {
        MBAR_INIT(mb0, 1);
        MBAR_INIT(mb1, 1);
        s_next = atomicAdd(&g_ticket, 1);
    }
    __syncthreads();
    int t = s_next;
    int i = 0, j = 0;
    if (t < NTT) {
        decode_tile(t, i, j);
        if (tid == 0) {
            MBAR_EXPECT(mb0, 32768);
            BULK16K(sb + SM_A0, g_X8 + (size_t)(i * 4 + 0) * 16384, mb0);
            BULK16K(sb + SM_B0, g_X8 + (size_t)(j * 4 + 0) * 16384, mb0);
        }
    }

    while (t < NTT) {
        // ---- zero-fill output blocks (i,j) and mirror (fire & forget) ----
        {
            const float4 z = make_float4(0.f, 0.f, 0.f, 0.f);
#pragma unroll
            for (int q = 0; q < 16; q++) {
                int lin = tid + q * TPB;
                int r = lin >> 5, c4 = lin & 31;
                *reinterpret_cast<float4*>(out + (size_t)(i * 128 + r) * N + j * 128 + c4 * 4) = z;
            }
            if (i != j) {
#pragma unroll
                for (int q = 0; q < 16; q++) {
                    int lin = tid + q * TPB;
                    int r = lin >> 5, c4 = lin & 31;
                    *reinterpret_cast<float4*>(out + (size_t)(j * 128 + r) * N + i * 128 + c4 * 4) = z;
                }
            }
        }

        float acc[2][8][4];
#pragma unroll
        for (int mf = 0; mf < 2; mf++)
#pragma unroll
            for (int nf = 0; nf < 8; nf++)
#pragma unroll
                for (int ri = 0; ri < 4; ri++) acc[mf][nf][ri] = 0.0f;

        int nt = t, ni = i, nj = j;
        for (int kc = 0; kc < 4; kc++) {
            const int b = kc & 1;
            if (b == 0) { MBAR_WAIT(mb0, (uint32_t)ph0); ph0 ^= 1; }
            else        { MBAR_WAIT(mb1, (uint32_t)ph1); ph1 ^= 1; }
            __syncthreads();          // all threads done with the OTHER buffer

            if (kc == 0 && tid == 0) s_next = atomicAdd(&g_ticket, 1);

            if (kc < 3) {
                if (tid == 0) {
                    uint32_t mbn = b ? mb0 : mb1;
                    uint32_t ap  = sb + (b ? SM_A0 : SM_A1);
                    uint32_t bp  = sb + (b ? SM_B0 : SM_B1);
                    MBAR_EXPECT(mbn, 32768);
                    BULK16K(ap, g_X8 + (size_t)(i * 4 + kc + 1) * 16384, mbn);
                    BULK16K(bp, g_X8 + (size_t)(j * 4 + kc + 1) * 16384, mbn);
                }
            } else {
                nt = s_next;          // published by kc==1..3 barriers
                if (nt < NTT) {
                    decode_tile(nt, ni, nj);
                    if (tid == 0) {   // kc==3: b==1 -> next chunk0 goes to buf0/mb0
                        MBAR_EXPECT(mb0, 32768);
                        BULK16K(sb + SM_A0, g_X8 + (size_t)(ni * 4 + 0) * 16384, mb0);
                        BULK16K(sb + SM_B0, g_X8 + (size_t)(nj * 4 + 0) * 16384, mb0);
                    }
                }
            }

            const uint32_t abase = sb + (b ? SM_A1 : SM_A0);
            const uint32_t bbase = sb + (b ? SM_B1 : SM_B0);

#pragma unroll
            for (int ks = 0; ks < 4; ks++) {
                const int sg = ks * 2;
                uint32_t a0[4], a1[4];
                {
                    int r0 = wr * 32 + a_r;
                    ldsm4(a0, abase + r0 * 128 + (((sg + a_s) ^ (r0 & 7)) << 4));
                    int r1 = r0 + 16;
                    ldsm4(a1, abase + r1 * 128 + (((sg + a_s) ^ (r1 & 7)) << 4));
                }
                uint32_t bfr[4][4];
#pragma unroll
                for (int q = 0; q < 4; q++) {
                    int n = wc * 64 + q * 16 + b_n;
                    ldsm4(bfr[q], bbase + n * 128 + (((sg + b_s) ^ (n & 7)) << 4));
                }
#pragma unroll
                for (int nf = 0; nf < 8; nf++) {
                    mma_fp8(acc[0][nf], a0, &bfr[nf >> 1][(nf & 1) * 2]);
                    mma_fp8(acc[1][nf], a1, &bfr[nf >> 1][(nf & 1) * 2]);
                }
            }
        }

        // ---- stage C: word w' = wc*32 + (lane&3)*8 + nf  (nf-contiguous) ----
#pragma unroll
        for (int mf = 0; mf < 2; mf++)
#pragma unroll
            for (int rp = 0; rp < 2; rp++) {
                int r = wr * 32 + mf * 16 + (lane >> 2) + rp * 8;
                uint32_t* dst = CsW + r * CSTR + wc * 32 + (lane & 3) * 8;
                uint4 w0, w1;
                w0.x = pack_bf16x2(acc[mf][0][rp*2], acc[mf][0][rp*2+1]);
                w0.y = pack_bf16x2(acc[mf][1][rp*2], acc[mf][1][rp*2+1]);
                w0.z = pack_bf16x2(acc[mf][2][rp*2], acc[mf][2][rp*2+1]);
                w0.w = pack_bf16x2(acc[mf][3][rp*2], acc[mf][3][rp*2+1]);
                w1.x = pack_bf16x2(acc[mf][4][rp*2], acc[mf][4][rp*2+1]);
                w1.y = pack_bf16x2(acc[mf][5][rp*2], acc[mf][5][rp*2+1]);
                w1.z = pack_bf16x2(acc[mf][6][rp*2], acc[mf][6][rp*2+1]);
                w1.w = pack_bf16x2(acc[mf][7][rp*2], acc[mf][7][rp*2+1]);
                *reinterpret_cast<uint4*>(dst)     = w0;
                *reinterpret_cast<uint4*>(dst + 4) = w1;
            }
        __syncthreads();

        // ---- scans with SIMD-max fast path ----
        float tv[RT]; int ti[RT];
#pragma unroll
        for (int q = 0; q < RT; q++) { tv[q] = -1e30f; ti[q] = 0; }

        if (tid < 128) {
            // row scan: row r, 16 groups of 4 words (8 values)
            const int r = tid;
            const uint32_t* base = CsW + r * CSTR;
            for (int g = 0; g < 16; g++) {
                uint4 qw = *reinterpret_cast<const uint4*>(base + 4 * g);
                __nv_bfloat162 m = __hmax2(__hmax2(as_bf2(qw.x), as_bf2(qw.y)),
                                           __hmax2(as_bf2(qw.z), as_bf2(qw.w)));
                float mx = fmaxf(__low2float(m), __high2float(m));
                if (mx > tv[RT - 1]) {
                    uint32_t ws[4] = {qw.x, qw.y, qw.z, qw.w};
#pragma unroll
                    for (int k = 0; k < 4; k++) {
                        int w = 4 * g + k;
                        int c = ((w >> 5) << 6) + ((w & 7) << 3) + (((w >> 3) & 3) << 1);
                        float v0 = bflo(ws[k]), v1 = bfhi(ws[k]);
#pragma unroll
                        for (int h = 0; h < 2; h++) {
                            float v = h ? v1 : v0;
                            if (v > tv[RT - 1]) {
                                tv[RT - 1] = v; ti[RT - 1] = j * 128 + c + h;
#pragma unroll
                                for (int p = RT - 1; p > 0; p--)
                                    if (tv[p] > tv[p - 1]) {
                                        float fv = tv[p]; tv[p] = tv[p-1]; tv[p-1] = fv;
                                        int   fi = ti[p]; ti[p] = ti[p-1]; ti[p-1] = fi;
                                    }
                            }
                        }
                    }
                }
            }
            float2* dst = &g_cand[((size_t)(i * 128 + r) * 64 + j) * 8];
#pragma unroll
            for (int q = 0; q < RT; q++)
                dst[q] = make_float2(tv[q], __int_as_float(ti[q]));
        } else if (i != j) {
            // col scan: col c, 32 groups of 4 rows
            const int c = tid - 128;
            const int cc = c & 63;
            const int wprime = ((c >> 6) << 5) + (((cc >> 1) & 3) << 3) + (cc >> 3);
            const bool odd = cc & 1;
            const uint32_t* base = CsW + wprime;
            for (int g = 0; g < 32; g++) {
                uint32_t w0 = base[(4*g + 0) * CSTR];
                uint32_t w1 = base[(4*g + 1) * CSTR];
                uint32_t w2 = base[(4*g + 2) * CSTR];
                uint32_t w3 = base[(4*g + 3) * CSTR];
                float v0 = odd ? bfhi(w0) : bflo(w0);
                float v1 = odd ? bfhi(w1) : bflo(w1);
                float v2 = odd ? bfhi(w2) : bflo(w2);
                float v3 = odd ? bfhi(w3) : bflo(w3);
                float mx = fmaxf(fmaxf(v0, v1), fmaxf(v2, v3));
                if (mx > tv[RT - 1]) {
                    float vs[4] = {v0, v1, v2, v3};
#pragma unroll
                    for (int k = 0; k < 4; k++) {
                        float v = vs[k];
                        if (v > tv[RT - 1]) {
                            tv[RT - 1] = v; ti[RT - 1] = i * 128 + 4*g + k;
#pragma unroll
                            for (int p = RT - 1; p > 0; p--)
                                if (tv[p] > tv[p - 1]) {
                                    float fv = tv[p]; tv[p] = tv[p-1]; tv[p-1] = fv;
                                    int   fi = ti[p]; ti[p] = ti[p-1]; ti[p-1] = fi;
                                }
                        }
                    }
                }
            }
            float2* dst = &g_cand[((size_t)(j * 128 + c) * 64 + i) * 8];
#pragma unroll
            for (int q = 0; q < RT; q++)
                dst[q] = make_float2(tv[q], __int_as_float(ti[q]));
        }

        t = nt; i = ni; j = nj;
        // CsW reuse protected by next tile's mainloop barriers
    }
}

// ===========================================================================
// Kernel 3: per-row merge of 64 sorted 8-lists -> top-12, exact fp32 rescore,
// top-5 (jax tie rule), softmax, scatter.  One warp per row.
// ===========================================================================
__global__ __launch_bounds__(256) void merge_rescore(float* __restrict__ out) {
    const int wid = threadIdx.x >> 5, lane = threadIdx.x & 31;
    const int row = blockIdx.x * 8 + wid;

    const float2* base = g_cand + (size_t)row * 512;
    int h0 = 0, h1 = 0;
    float2 e;
    e = base[lane * 8];        float cv0 = e.x; int ci0 = __float_as_int(e.y);
    e = base[(lane + 32) * 8]; float cv1 = e.x; int ci1 = __float_as_int(e.y);

    int selidx[SEL];
#pragma unroll
    for (int it = 0; it < SEL; it++) {
        bool p0 = (cv0 > cv1) || (cv0 == cv1 && ci0 <= ci1);
        float v = p0 ? cv0 : cv1;
        int  ix = p0 ? ci0 : ci1;
        float bv = v; int bi = ix, bl = lane;
#pragma unroll
        for (int o = 16; o; o >>= 1) {
            float ov = __shfl_xor_sync(0xffffffffu, bv, o);
            int   oi = __shfl_xor_sync(0xffffffffu, bi, o);
            int   ol = __shfl_xor_sync(0xffffffffu, bl, o);
            if (ov > bv || (ov == bv && oi < bi)) { bv = ov; bi = oi; bl = ol; }
        }
        selidx[it] = bi;
        if (bl == lane) {
            if (p0) {
                h0++;
                if (h0 < 8) { e = base[lane * 8 + h0]; cv0 = e.x; ci0 = __float_as_int(e.y); }
                else cv0 = -1e30f;
            } else {
                h1++;
                if (h1 < 8) { e = base[(lane + 32) * 8 + h1]; cv1 = e.x; ci1 = __float_as_int(e.y); }
                else cv1 = -1e30f;
            }
        }
    }

    // ---- exact fp32 rescore of the 12 selected ----
    float xr[16];
#pragma unroll
    for (int q = 0; q < 16; q++) xr[q] = g_Xn[(size_t)row * D + q * 32 + lane];

    float myv = -1e30f; int myi = 0x7fffffff;
#pragma unroll
    for (int c = 0; c < SEL; c++) {
        int idx = selidx[c];
        const float* Xc = g_Xn + (size_t)idx * D;
        float s = 0.f;
#pragma unroll
        for (int q = 0; q < 16; q++) s = fmaf(xr[q], Xc[q * 32 + lane], s);
#pragma unroll
        for (int o = 16; o; o >>= 1) s += __shfl_xor_sync(0xffffffffu, s, o);
        if (lane == c) { myv = s; myi = idx; }
    }

    float sv[5]; int si[5];
#pragma unroll
    for (int r5 = 0; r5 < 5; r5++) {
        float v = myv; int ix = myi;
#pragma unroll
        for (int o = 16; o; o >>= 1) {
            float ov = __shfl_xor_sync(0xffffffffu, v, o);
            int   oi = __shfl_xor_sync(0xffffffffu, ix, o);
            if (ov > v || (ov == v && oi < ix)) { v = ov; ix = oi; }
        }
        sv[r5] = v; si[r5] = ix;
        if (myi == ix) { myv = -1e30f; myi = 0x7fffffff; }
    }

    if (lane == 0) {
        float m = sv[0];
        float e0 = expf((sv[0] - m) * TEMP_INV);
        float e1 = expf((sv[1] - m) * TEMP_INV);
        float e2 = expf((sv[2] - m) * TEMP_INV);
        float e3 = expf((sv[3] - m) * TEMP_INV);
        float e4 = expf((sv[4] - m) * TEMP_INV);
        float inv = 1.0f / (e0 + e1 + e2 + e3 + e4);
        float* o = out + (size_t)row * N;
        o[si[0]] = e0 * inv; o[si[1]] = e1 * inv; o[si[2]] = e2 * inv;
        o[si[3]] = e3 * inv; o[si[4]] = e4 * inv;
    }
}

// ===========================================================================
extern "C" void kernel_launch(void* const* d_in, const int* in_sizes, int n_in,
                              void* d_out, int out_size) {
    (void)in_sizes; (void)n_in; (void)out_size;
    const float* X   = (const float*)d_in[0];
    float*       out = (float*)d_out;

    cudaFuncSetAttribute(tile_kernel, cudaFuncAttributeMaxDynamicSharedMemorySize, SMEM_TOTAL);

    normalize_kernel<<<N / 8, 256>>>(X);
    tile_kernel<<<G2, TPB, SMEM_TOTAL>>>(out);
    merge_rescore<<<N / 8, 256>>>(out);
}